// round 2
// baseline (speedup 1.0000x reference)
#include <cuda_runtime.h>

#define MTOT 4096          // B*S
#define DM   1024          // d_model
#define SLEN 2048
#define NHEAD 16
#define DHEAD 64

// Scratch (static device globals: allocation-free per harness rules)
__device__ float g_Q[MTOT * DM];
__device__ float g_K[MTOT * DM];
__device__ float g_V[MTOT * DM];
__device__ float g_C[MTOT * DM];   // attention context
__device__ float g_H[MTOT * DM];   // pre-LN (ctx@Wo + bo + residual)

// ---------------------------------------------------------------------------
// SGEMM: C[M,N] = A[M,K] @ W[K,N] + bias[N] (+ res[M,N])   M=MTOT, N=K=DM
// 128x128 block tile, BK=16, 256 threads, 8x8 register tile.
// ---------------------------------------------------------------------------
__global__ __launch_bounds__(256, 2)
void sgemm_kernel(const float* __restrict__ A, const float* __restrict__ W,
                  const float* __restrict__ bias, const float* __restrict__ res,
                  float* __restrict__ C)
{
    __shared__ float As[16][128];
    __shared__ float Bs[16][128];

    const int tid = threadIdx.x;
    const int tx  = tid & 15;
    const int ty  = tid >> 4;
    const int m0  = blockIdx.y * 128;
    const int n0  = blockIdx.x * 128;

    float acc[8][8];
#pragma unroll
    for (int i = 0; i < 8; i++)
#pragma unroll
        for (int j = 0; j < 8; j++) acc[i][j] = 0.f;

    for (int k0 = 0; k0 < DM; k0 += 16) {
#pragma unroll
        for (int i = 0; i < 2; i++) {
            int f  = tid + i * 256;               // 0..511 float4 slots
            int ar = f >> 2;                      // 0..127
            int ac = (f & 3) << 2;                // 0,4,8,12
            float4 av = *(const float4*)(A + (size_t)(m0 + ar) * DM + k0 + ac);
            As[ac + 0][ar] = av.x;
            As[ac + 1][ar] = av.y;
            As[ac + 2][ar] = av.z;
            As[ac + 3][ar] = av.w;
            int br = f >> 5;                      // 0..15
            int bc = (f & 31) << 2;               // 0..124
            *(float4*)&Bs[br][bc] =
                *(const float4*)(W + (size_t)(k0 + br) * DM + n0 + bc);
        }
        __syncthreads();
#pragma unroll
        for (int k = 0; k < 16; k++) {
            float a[8], b[8];
            *(float4*)(a)     = *(const float4*)&As[k][ty * 8];
            *(float4*)(a + 4) = *(const float4*)&As[k][ty * 8 + 4];
            *(float4*)(b)     = *(const float4*)&Bs[k][tx * 8];
            *(float4*)(b + 4) = *(const float4*)&Bs[k][tx * 8 + 4];
#pragma unroll
            for (int i = 0; i < 8; i++)
#pragma unroll
                for (int j = 0; j < 8; j++)
                    acc[i][j] = fmaf(a[i], b[j], acc[i][j]);
        }
        __syncthreads();
    }

#pragma unroll
    for (int i = 0; i < 8; i++) {
        size_t r = (size_t)(m0 + ty * 8 + i);
#pragma unroll
        for (int j = 0; j < 8; j += 4) {
            int cc = n0 + tx * 8 + j;
            float4 o;
            o.x = acc[i][j + 0] + bias[cc + 0];
            o.y = acc[i][j + 1] + bias[cc + 1];
            o.z = acc[i][j + 2] + bias[cc + 2];
            o.w = acc[i][j + 3] + bias[cc + 3];
            if (res) {
                float4 rv = *(const float4*)(res + r * DM + cc);
                o.x += rv.x; o.y += rv.y; o.z += rv.z; o.w += rv.w;
            }
            *(float4*)(C + r * DM + cc) = o;
        }
    }
}

// ---------------------------------------------------------------------------
// Flash attention, fp32. Grid: (S/64, H, B). 256 threads.
// Thread (row = tid>>2, sub = tid&3):
//   keys owned:  j = 4*c + sub           (c = 0..15)  -> conflict-free K reads
//   dims owned:  chunks (4*t + sub)*4..+3 (t = 0..3)  -> conflict-free V reads
// P exchanged within the 4-lane row group via shfl (no P smem).
// ---------------------------------------------------------------------------
#define QPAD 68   // floats per row in smem tiles (multiple of 4, 17 f4 -> conflict-free)

__global__ __launch_bounds__(256)
void attn_kernel(const float* __restrict__ Q, const float* __restrict__ K,
                 const float* __restrict__ V, float* __restrict__ O)
{
    extern __shared__ float sm[];
    float* Qs = sm;                    // 64 * QPAD
    float* Ks = sm + 64 * QPAD;
    float* Vs = sm + 2 * 64 * QPAD;

    const int tid = threadIdx.x;
    const int row = tid >> 2;
    const int sub = tid & 3;
    const int qt  = blockIdx.x;
    const int h   = blockIdx.y;
    const int b   = blockIdx.z;
    const size_t base = (size_t)b * SLEN * DM + (size_t)h * DHEAD;
    const int q0 = qt * 64;

    // Load Q tile, pre-scaled by 1/sqrt(Dh) = 0.125
#pragma unroll
    for (int i = 0; i < 4; i++) {
        int f = tid + i * 256;
        int r = f >> 4;
        int c = (f & 15) << 2;
        float4 v = *(const float4*)(Q + base + (size_t)(q0 + r) * DM + c);
        v.x *= 0.125f; v.y *= 0.125f; v.z *= 0.125f; v.w *= 0.125f;
        *(float4*)&Qs[r * QPAD + c] = v;
    }

    float m = -1e30f, l = 0.f;
    float4 a4[4];
#pragma unroll
    for (int t = 0; t < 4; t++) a4[t] = make_float4(0.f, 0.f, 0.f, 0.f);

    for (int t0 = 0; t0 < SLEN; t0 += 64) {
        __syncthreads();
#pragma unroll
        for (int i = 0; i < 4; i++) {
            int f = tid + i * 256;
            int r = f >> 4;
            int c = (f & 15) << 2;
            *(float4*)&Ks[r * QPAD + c] =
                *(const float4*)(K + base + (size_t)(t0 + r) * DM + c);
            *(float4*)&Vs[r * QPAD + c] =
                *(const float4*)(V + base + (size_t)(t0 + r) * DM + c);
        }
        __syncthreads();

        // S = Q K^T for this thread's 16 keys
        float s[16];
#pragma unroll
        for (int c = 0; c < 16; c++) s[c] = 0.f;
#pragma unroll
        for (int half = 0; half < 2; half++) {
            float4 qf[8];
#pragma unroll
            for (int t = 0; t < 8; t++)
                qf[t] = *(const float4*)&Qs[row * QPAD + half * 32 + t * 4];
#pragma unroll
            for (int c = 0; c < 16; c++) {
                const float* kp = &Ks[(c * 4 + sub) * QPAD + half * 32];
                float4 sv = make_float4(0.f, 0.f, 0.f, 0.f);
#pragma unroll
                for (int t = 0; t < 8; t++) {
                    float4 kv = *(const float4*)(kp + t * 4);
                    sv.x = fmaf(qf[t].x, kv.x, sv.x);
                    sv.y = fmaf(qf[t].y, kv.y, sv.y);
                    sv.z = fmaf(qf[t].z, kv.z, sv.z);
                    sv.w = fmaf(qf[t].w, kv.w, sv.w);
                }
                s[c] += (sv.x + sv.y) + (sv.z + sv.w);
            }
        }

        // Online softmax over the 4-lane row group
        float tmax = s[0];
#pragma unroll
        for (int c = 1; c < 16; c++) tmax = fmaxf(tmax, s[c]);
        tmax = fmaxf(tmax, __shfl_xor_sync(0xffffffffu, tmax, 1));
        tmax = fmaxf(tmax, __shfl_xor_sync(0xffffffffu, tmax, 2));
        float mnew = fmaxf(m, tmax);
        float corr = __expf(m - mnew);
        m = mnew;

        float p[16];
        float ls = 0.f;
#pragma unroll
        for (int c = 0; c < 16; c++) { p[c] = __expf(s[c] - mnew); ls += p[c]; }
        ls += __shfl_xor_sync(0xffffffffu, ls, 1);
        ls += __shfl_xor_sync(0xffffffffu, ls, 2);
        l = l * corr + ls;

#pragma unroll
        for (int t = 0; t < 4; t++) {
            a4[t].x *= corr; a4[t].y *= corr; a4[t].z *= corr; a4[t].w *= corr;
        }

        // ctx += P @ V   (key j owned by lane sub=j&3, slot j>>2)
#pragma unroll
        for (int j = 0; j < 64; j++) {
            float pj = __shfl_sync(0xffffffffu, p[j >> 2], j & 3, 4);
            const float* vp = &Vs[j * QPAD];
#pragma unroll
            for (int t = 0; t < 4; t++) {
                float4 vv = *(const float4*)(vp + (t * 4 + sub) * 4);
                a4[t].x = fmaf(pj, vv.x, a4[t].x);
                a4[t].y = fmaf(pj, vv.y, a4[t].y);
                a4[t].z = fmaf(pj, vv.z, a4[t].z);
                a4[t].w = fmaf(pj, vv.w, a4[t].w);
            }
        }
    }

    float inv = 1.f / l;
    float* op = O + base + (size_t)(q0 + row) * DM;
#pragma unroll
    for (int t = 0; t < 4; t++) {
        float4 o = a4[t];
        o.x *= inv; o.y *= inv; o.z *= inv; o.w *= inv;
        *(float4*)(op + (t * 4 + sub) * 4) = o;
    }
}

// ---------------------------------------------------------------------------
// LayerNorm over last dim (1024). One block per row, 256 threads x 4 elems.
// ---------------------------------------------------------------------------
__global__ __launch_bounds__(256)
void ln_kernel(const float* __restrict__ H, const float* __restrict__ gamma,
               const float* __restrict__ beta, float* __restrict__ O)
{
    __shared__ float red[16];
    const int r = blockIdx.x;
    const int tid = threadIdx.x;
    const float* h = H + (size_t)r * DM;

    float4 v = *(const float4*)(h + tid * 4);
    float sum = v.x + v.y + v.z + v.w;
    float sq  = v.x * v.x + v.y * v.y + v.z * v.z + v.w * v.w;
#pragma unroll
    for (int o = 16; o > 0; o >>= 1) {
        sum += __shfl_xor_sync(0xffffffffu, sum, o);
        sq  += __shfl_xor_sync(0xffffffffu, sq,  o);
    }
    int wid = tid >> 5;
    if ((tid & 31) == 0) { red[wid] = sum; red[8 + wid] = sq; }
    __syncthreads();
    if (tid < 32) {
        float s2 = (tid < 8) ? red[tid]     : 0.f;
        float q2 = (tid < 8) ? red[8 + tid] : 0.f;
#pragma unroll
        for (int o = 4; o > 0; o >>= 1) {
            s2 += __shfl_xor_sync(0xffffffffu, s2, o);
            q2 += __shfl_xor_sync(0xffffffffu, q2, o);
        }
        if (tid == 0) { red[0] = s2; red[1] = q2; }
    }
    __syncthreads();
    float mu   = red[0] * (1.f / 1024.f);
    float var  = red[1] * (1.f / 1024.f) - mu * mu;
    float rstd = rsqrtf(var + 1e-12f);

    float4 g = *(const float4*)(gamma + tid * 4);
    float4 t = *(const float4*)(beta  + tid * 4);
    float4 o;
    o.x = (v.x - mu) * rstd * g.x + t.x;
    o.y = (v.y - mu) * rstd * g.y + t.y;
    o.z = (v.z - mu) * rstd * g.z + t.z;
    o.w = (v.w - mu) * rstd * g.w + t.w;
    *(float4*)(O + (size_t)r * DM + tid * 4) = o;
}

// ---------------------------------------------------------------------------
extern "C" void kernel_launch(void* const* d_in, const int* in_sizes, int n_in,
                              void* d_out, int out_size)
{
    const float* X     = (const float*)d_in[0];
    const float* Wq    = (const float*)d_in[1];
    const float* bq    = (const float*)d_in[2];
    const float* Wk    = (const float*)d_in[3];
    const float* bk    = (const float*)d_in[4];
    const float* Wv    = (const float*)d_in[5];
    const float* bv    = (const float*)d_in[6];
    const float* Wo    = (const float*)d_in[7];
    const float* bo    = (const float*)d_in[8];
    const float* gamma = (const float*)d_in[9];
    const float* beta  = (const float*)d_in[10];
    float* out = (float*)d_out;

    float *Qp, *Kp, *Vp, *Cp, *Hp;
    cudaGetSymbolAddress((void**)&Qp, g_Q);
    cudaGetSymbolAddress((void**)&Kp, g_K);
    cudaGetSymbolAddress((void**)&Vp, g_V);
    cudaGetSymbolAddress((void**)&Cp, g_C);
    cudaGetSymbolAddress((void**)&Hp, g_H);

    dim3 gg(DM / 128, MTOT / 128);
    sgemm_kernel<<<gg, 256>>>(X, Wq, bq, nullptr, Qp);
    sgemm_kernel<<<gg, 256>>>(X, Wk, bk, nullptr, Kp);
    sgemm_kernel<<<gg, 256>>>(X, Wv, bv, nullptr, Vp);

    const int attn_smem = 3 * 64 * QPAD * (int)sizeof(float);  // 52224 B
    cudaFuncSetAttribute(attn_kernel, cudaFuncAttributeMaxDynamicSharedMemorySize,
                         attn_smem);
    dim3 ga(SLEN / 64, NHEAD, 2);
    attn_kernel<<<ga, 256, attn_smem>>>(Qp, Kp, Vp, Cp);

    sgemm_kernel<<<gg, 256>>>(Cp, Wo, bo, X, Hp);   // + residual
    ln_kernel<<<MTOT, 256>>>(Hp, gamma, beta, out);
}

// round 4
// speedup vs baseline: 4.1714x; 4.1714x over previous
#include <cuda_runtime.h>
#include <cuda_bf16.h>
#include <cstdint>

#define MTOT 4096          // B*S
#define DM   1024
#define SLEN 2048
#define NHEAD 16
#define DHEAD 64

typedef __nv_bfloat16 bf16;

// ---------------- scratch ---------------------------------------------------
__device__ bf16 g_Qh[MTOT * DM], g_Ql[MTOT * DM];
__device__ bf16 g_Kh[MTOT * DM], g_Kl[MTOT * DM];
__device__ bf16 g_Vh[MTOT * DM], g_Vl[MTOT * DM];
__device__ bf16 g_Ch[MTOT * DM], g_Cl[MTOT * DM];
__device__ bf16 g_Xh[MTOT * DM], g_Xl[MTOT * DM];
__device__ bf16 g_Wth[4][DM * DM], g_Wtl[4][DM * DM];
__device__ float g_H[MTOT * DM];

// ---------------- helpers ---------------------------------------------------
__device__ __forceinline__ uint32_t smem_u32(const void* p) {
    uint32_t a;
    asm("{ .reg .u64 t; cvta.to.shared.u64 t, %1; cvt.u32.u64 %0, t; }"
        : "=r"(a) : "l"(p));
    return a;
}
__device__ __forceinline__ void cp16(uint32_t dst, const void* src) {
    asm volatile("cp.async.cg.shared.global [%0], [%1], 16;"
                 :: "r"(dst), "l"(src) : "memory");
}
#define CP_COMMIT() asm volatile("cp.async.commit_group;" ::: "memory")
#define CP_WAIT(n)  asm volatile("cp.async.wait_group %0;" :: "n"(n) : "memory")

__device__ __forceinline__ void ldsm4(uint32_t* r, uint32_t a) {
    asm volatile("ldmatrix.sync.aligned.m8n8.x4.shared.b16 {%0,%1,%2,%3}, [%4];"
                 : "=r"(r[0]), "=r"(r[1]), "=r"(r[2]), "=r"(r[3]) : "r"(a));
}
__device__ __forceinline__ void ldsm4t(uint32_t* r, uint32_t a) {
    asm volatile("ldmatrix.sync.aligned.m8n8.x4.trans.shared.b16 {%0,%1,%2,%3}, [%4];"
                 : "=r"(r[0]), "=r"(r[1]), "=r"(r[2]), "=r"(r[3]) : "r"(a));
}
__device__ __forceinline__ void mma16816(float* c, const uint32_t* a,
                                         const uint32_t* b) {
    asm volatile(
        "mma.sync.aligned.m16n8k16.row.col.f32.bf16.bf16.f32 "
        "{%0,%1,%2,%3}, {%4,%5,%6,%7}, {%8,%9}, {%0,%1,%2,%3};"
        : "+f"(c[0]), "+f"(c[1]), "+f"(c[2]), "+f"(c[3])
        : "r"(a[0]), "r"(a[1]), "r"(a[2]), "r"(a[3]), "r"(b[0]), "r"(b[1]));
}
// pack (v0 -> low, v1 -> high) into bf16x2; also produce the residual pair
__device__ __forceinline__ void split_pair(float v0, float v1,
                                           uint32_t& hi, uint32_t& lo) {
    uint32_t h;
    asm("cvt.rn.bf16x2.f32 %0, %1, %2;" : "=r"(h) : "f"(v1), "f"(v0));
    __nv_bfloat162 hb = *reinterpret_cast<__nv_bfloat162*>(&h);
    float r0 = __low2float(hb), r1 = __high2float(hb);
    uint32_t l;
    asm("cvt.rn.bf16x2.f32 %0, %1, %2;" : "=r"(l) : "f"(v1 - r1), "f"(v0 - r0));
    hi = h; lo = l;
}

// ---------------------------------------------------------------------------
// split: fp32 -> (hi, lo) bf16
// ---------------------------------------------------------------------------
__global__ __launch_bounds__(256)
void split_kernel(const float* __restrict__ X, bf16* __restrict__ H,
                  bf16* __restrict__ L)
{
    int i = (blockIdx.x * 256 + threadIdx.x) * 4;
    float4 v = *(const float4*)(X + i);
    uint32_t h0, l0, h1, l1;
    split_pair(v.x, v.y, h0, l0);
    split_pair(v.z, v.w, h1, l1);
    *(uint32_t*)(H + i)     = h0;
    *(uint32_t*)(H + i + 2) = h1;
    *(uint32_t*)(L + i)     = l0;
    *(uint32_t*)(L + i + 2) = l1;
}

// ---------------------------------------------------------------------------
// transpose + split: W [K,N] fp32 -> Wt hi/lo [N,K] bf16
// ---------------------------------------------------------------------------
__global__ __launch_bounds__(256)
void transpose_split_kernel(const float* __restrict__ W,
                            bf16* __restrict__ Th, bf16* __restrict__ Tl)
{
    __shared__ float t[32][33];
    int n0 = blockIdx.x * 32, k0 = blockIdx.y * 32;
    int tx = threadIdx.x, ty = threadIdx.y;   // 32 x 8
#pragma unroll
    for (int j = 0; j < 4; j++)
        t[ty + j * 8][tx] = W[(size_t)(k0 + ty + j * 8) * DM + n0 + tx];
    __syncthreads();
#pragma unroll
    for (int j = 0; j < 4; j++) {
        float v = t[tx][ty + j * 8];
        bf16 h = __float2bfloat16(v);
        size_t o = (size_t)(n0 + ty + j * 8) * DM + k0 + tx;
        Th[o] = h;
        Tl[o] = __float2bfloat16(v - __bfloat162float(h));
    }
}

// ---------------------------------------------------------------------------
// mma.sync bf16-split GEMM: C[4096,1024] = A @ Wt^T
// CTA 128x128, BK=32, 8 warps (4m x 2n), warp tile 32x64.
// Epilogue: either bf16 hi/lo out with scale, or fp32 out (+bias+res).
// ---------------------------------------------------------------------------
#define GROWB 80                  // bytes per padded smem row (32 bf16 + pad)
#define GTILE (128 * GROWB)       // 10240
#define GSTG  (4 * GTILE)         // 40960 per stage
#define GSMEM (2 * GSTG)          // 81920

__global__ __launch_bounds__(256, 2)
void gemm_mma(const bf16* __restrict__ Ah, const bf16* __restrict__ Al,
              const bf16* __restrict__ Bh, const bf16* __restrict__ Bl,
              const float* __restrict__ bias, const float* __restrict__ res,
              float* __restrict__ Cf, bf16* __restrict__ Chi,
              bf16* __restrict__ Clo, float scale)
{
    extern __shared__ __align__(16) char smraw[];
    const uint32_t sb = smem_u32(smraw);
    const int tid = threadIdx.x;
    const int lane = tid & 31, wid = tid >> 5;
    const int wm = wid >> 1, wn = wid & 1;
    const int m0 = blockIdx.y * 128, n0 = blockIdx.x * 128;

    const bf16* srcs[4] = {Ah, Al, Bh, Bl};

    auto load = [&](int ki, int st) {
        const int k0 = ki * 32;
#pragma unroll
        for (int t = 0; t < 4; t++) {
            const int rb = (t < 2) ? m0 : n0;
            const bf16* s = srcs[t];
#pragma unroll
            for (int i = 0; i < 2; i++) {
                int idx = tid + i * 256;
                int row = idx >> 2, slot = idx & 3;
                cp16(sb + st * GSTG + t * GTILE + row * GROWB + slot * 16,
                     s + (size_t)(rb + row) * DM + k0 + slot * 8);
            }
        }
    };

    float acc[2][8][4];
#pragma unroll
    for (int mt = 0; mt < 2; mt++)
#pragma unroll
        for (int nt = 0; nt < 8; nt++)
#pragma unroll
            for (int e = 0; e < 4; e++) acc[mt][nt][e] = 0.f;

    load(0, 0); CP_COMMIT();

    for (int ki = 0; ki < 32; ki++) {
        const int st = ki & 1;
        if (ki < 31) { load(ki + 1, st ^ 1); CP_COMMIT(); CP_WAIT(1); }
        else         { CP_WAIT(0); }
        __syncthreads();
        const uint32_t base = sb + st * GSTG;
#pragma unroll
        for (int ks = 0; ks < 2; ks++) {
            uint32_t ah[2][4], al[2][4];
#pragma unroll
            for (int mt = 0; mt < 2; mt++) {
                uint32_t r = wm * 32 + mt * 16 + (lane & 15);
                uint32_t cb = (ks * 16 + (lane >> 4) * 8) * 2;
                ldsm4(ah[mt], base + r * GROWB + cb);
                ldsm4(al[mt], base + GTILE + r * GROWB + cb);
            }
#pragma unroll
            for (int p = 0; p < 4; p++) {
                uint32_t r = wn * 64 + p * 16 + ((lane >> 4) & 1) * 8 + (lane & 7);
                uint32_t cb = (ks * 16 + ((lane >> 3) & 1) * 8) * 2;
                uint32_t bh[4], bl[4];
                ldsm4(bh, base + 2 * GTILE + r * GROWB + cb);
                ldsm4(bl, base + 3 * GTILE + r * GROWB + cb);
#pragma unroll
                for (int mt = 0; mt < 2; mt++) {
#pragma unroll
                    for (int q = 0; q < 2; q++) {
                        float* c = acc[mt][2 * p + q];
                        mma16816(c, ah[mt], bh + 2 * q);
                        mma16816(c, ah[mt], bl + 2 * q);
                        mma16816(c, al[mt], bh + 2 * q);
                    }
                }
            }
        }
        __syncthreads();
    }

    // epilogue
#pragma unroll
    for (int mt = 0; mt < 2; mt++) {
        int r0 = m0 + wm * 32 + mt * 16 + (lane >> 2);
#pragma unroll
        for (int nt = 0; nt < 8; nt++) {
            int c0 = n0 + wn * 64 + nt * 8 + (lane & 3) * 2;
            float b0 = bias[c0], b1 = bias[c0 + 1];
#pragma unroll
            for (int hr = 0; hr < 2; hr++) {
                int rr = r0 + hr * 8;
                float v0 = acc[mt][nt][hr * 2 + 0] + b0;
                float v1 = acc[mt][nt][hr * 2 + 1] + b1;
                size_t off = (size_t)rr * DM + c0;
                if (Cf) {
                    float2 rv = *(const float2*)(res + off);
                    float2 o; o.x = v0 + rv.x; o.y = v1 + rv.y;
                    *(float2*)(Cf + off) = o;
                } else {
                    uint32_t hp, lp;
                    split_pair(v0 * scale, v1 * scale, hp, lp);
                    *(uint32_t*)(Chi + off) = hp;
                    *(uint32_t*)(Clo + off) = lp;
                }
            }
        }
    }
}

// ---------------------------------------------------------------------------
// Tensor-core flash attention. Grid (SLEN/128, NHEAD, B). 256 threads, 8 warps.
// Warp w owns q rows [w*16, w*16+16). Q frags register-resident.
// Scores arrive pre-scaled by 0.125*log2(e) (folded into Q), softmax via exp2.
// ---------------------------------------------------------------------------
#define AROWB 144                 // 64 bf16 + pad, bytes
#define ATILE (64 * AROWB)        // 9216
#define ASTG  (4 * ATILE)         // 36864 per stage (Kh,Kl,Vh,Vl)
#define ASMEM (2 * ASTG)          // 73728

__global__ __launch_bounds__(256, 1)
void attn_mma(const bf16* __restrict__ Qh, const bf16* __restrict__ Ql,
              const bf16* __restrict__ Kh, const bf16* __restrict__ Kl,
              const bf16* __restrict__ Vh, const bf16* __restrict__ Vl,
              bf16* __restrict__ Ch, bf16* __restrict__ Cl)
{
    extern __shared__ __align__(16) char smraw[];
    const uint32_t sb = smem_u32(smraw);
    const int tid = threadIdx.x;
    const int lane = tid & 31, wid = tid >> 5;
    const int qt = blockIdx.x, hd = blockIdx.y, bb = blockIdx.z;
    const size_t gq0 = (size_t)bb * SLEN + qt * 128;   // global q-row base
    const size_t gk0 = (size_t)bb * SLEN;              // global key-row base
    const int gcol = hd * DHEAD;

    // ---- stage Q (hi at sb, lo at sb+18432; reuses pipeline stage 0) ----
#pragma unroll
    for (int i = 0; i < 8; i++) {
        int idx = tid + i * 256;              // 0..2047
        int t = idx >> 10;                    // 0 hi, 1 lo
        int rr = (idx >> 3) & 127;
        int ch = idx & 7;
        const bf16* s = t ? Ql : Qh;
        cp16(sb + t * 18432 + rr * AROWB + ch * 16,
             s + (gq0 + rr) * DM + gcol + ch * 8);
    }
    CP_COMMIT(); CP_WAIT(0);
    __syncthreads();

    uint32_t qfh[4][4], qfl[4][4];
#pragma unroll
    for (int ks = 0; ks < 4; ks++) {
        uint32_t r = wid * 16 + (lane & 15);
        uint32_t cb = (ks * 16 + (lane >> 4) * 8) * 2;
        ldsm4(qfh[ks], sb + r * AROWB + cb);
        ldsm4(qfl[ks], sb + 18432 + r * AROWB + cb);
    }
    __syncthreads();

    float oacc[8][4];
#pragma unroll
    for (int nd = 0; nd < 8; nd++)
#pragma unroll
        for (int e = 0; e < 4; e++) oacc[nd][e] = 0.f;
    float mx0 = -1e30f, mx1 = -1e30f, ls0 = 0.f, ls1 = 0.f;

    const bf16* kvsrc[4] = {Kh, Kl, Vh, Vl};
    auto loadkv = [&](int ti, int st) {
        const int t0 = ti * 64;
#pragma unroll
        for (int i = 0; i < 8; i++) {
            int idx = tid + i * 256;
            int t = idx >> 9;                 // tile 0..3
            int rr = (idx >> 3) & 63;
            int ch = idx & 7;
            cp16(sb + st * ASTG + t * ATILE + rr * AROWB + ch * 16,
                 kvsrc[t] + (gk0 + t0 + rr) * DM + gcol + ch * 8);
        }
    };

    loadkv(0, 0); CP_COMMIT();

    for (int ti = 0; ti < 32; ti++) {
        const int st = ti & 1;
        if (ti < 31) { loadkv(ti + 1, st ^ 1); CP_COMMIT(); CP_WAIT(1); }
        else         { CP_WAIT(0); }
        __syncthreads();
        const uint32_t kb = sb + st * ASTG;

        // ---- S = Q K^T ----
        float sacc[8][4];
#pragma unroll
        for (int nt = 0; nt < 8; nt++)
#pragma unroll
            for (int e = 0; e < 4; e++) sacc[nt][e] = 0.f;
#pragma unroll
        for (int ks = 0; ks < 4; ks++) {
#pragma unroll
            for (int p = 0; p < 4; p++) {
                uint32_t r = p * 16 + ((lane >> 4) & 1) * 8 + (lane & 7);
                uint32_t cb = (ks * 16 + ((lane >> 3) & 1) * 8) * 2;
                uint32_t kh4[4], kl4[4];
                ldsm4(kh4, kb + r * AROWB + cb);
                ldsm4(kl4, kb + ATILE + r * AROWB + cb);
#pragma unroll
                for (int q = 0; q < 2; q++) {
                    float* c = sacc[2 * p + q];
                    mma16816(c, qfh[ks], kh4 + 2 * q);
                    mma16816(c, qfh[ks], kl4 + 2 * q);
                    mma16816(c, qfl[ks], kh4 + 2 * q);
                }
            }
        }

        // ---- online softmax (two row-halves per thread) ----
        float t0 = -1e30f, t1 = -1e30f;
#pragma unroll
        for (int nt = 0; nt < 8; nt++) {
            t0 = fmaxf(t0, fmaxf(sacc[nt][0], sacc[nt][1]));
            t1 = fmaxf(t1, fmaxf(sacc[nt][2], sacc[nt][3]));
        }
        t0 = fmaxf(t0, __shfl_xor_sync(0xffffffffu, t0, 1));
        t0 = fmaxf(t0, __shfl_xor_sync(0xffffffffu, t0, 2));
        t1 = fmaxf(t1, __shfl_xor_sync(0xffffffffu, t1, 1));
        t1 = fmaxf(t1, __shfl_xor_sync(0xffffffffu, t1, 2));
        float mn0 = fmaxf(mx0, t0), mn1 = fmaxf(mx1, t1);
        float cr0 = exp2f(mx0 - mn0), cr1 = exp2f(mx1 - mn1);
        mx0 = mn0; mx1 = mn1;

        float ps0 = 0.f, ps1 = 0.f;
#pragma unroll
        for (int nt = 0; nt < 8; nt++) {
            sacc[nt][0] = exp2f(sacc[nt][0] - mn0); ps0 += sacc[nt][0];
            sacc[nt][1] = exp2f(sacc[nt][1] - mn0); ps0 += sacc[nt][1];
            sacc[nt][2] = exp2f(sacc[nt][2] - mn1); ps1 += sacc[nt][2];
            sacc[nt][3] = exp2f(sacc[nt][3] - mn1); ps1 += sacc[nt][3];
        }
        ps0 += __shfl_xor_sync(0xffffffffu, ps0, 1);
        ps0 += __shfl_xor_sync(0xffffffffu, ps0, 2);
        ps1 += __shfl_xor_sync(0xffffffffu, ps1, 1);
        ps1 += __shfl_xor_sync(0xffffffffu, ps1, 2);
        ls0 = ls0 * cr0 + ps0;
        ls1 = ls1 * cr1 + ps1;
#pragma unroll
        for (int nd = 0; nd < 8; nd++) {
            oacc[nd][0] *= cr0; oacc[nd][1] *= cr0;
            oacc[nd][2] *= cr1; oacc[nd][3] *= cr1;
        }

        // ---- ctx += P V ----
        const uint32_t vb = kb + 2 * ATILE;
#pragma unroll
        for (int kt = 0; kt < 4; kt++) {
            uint32_t ph[4], pl[4];
            split_pair(sacc[2 * kt][0],     sacc[2 * kt][1],     ph[0], pl[0]);
            split_pair(sacc[2 * kt][2],     sacc[2 * kt][3],     ph[1], pl[1]);
            split_pair(sacc[2 * kt + 1][0], sacc[2 * kt + 1][1], ph[2], pl[2]);
            split_pair(sacc[2 * kt + 1][2], sacc[2 * kt + 1][3], ph[3], pl[3]);
#pragma unroll
            for (int pd = 0; pd < 4; pd++) {
                uint32_t r = kt * 16 + (lane & 15);
                uint32_t cb = (pd * 16 + (lane >> 4) * 8) * 2;
                uint32_t vh4[4], vl4[4];
                ldsm4t(vh4, vb + r * AROWB + cb);
                ldsm4t(vl4, vb + ATILE + r * AROWB + cb);
#pragma unroll
                for (int q = 0; q < 2; q++) {
                    float* c = oacc[2 * pd + q];
                    mma16816(c, ph, vh4 + 2 * q);
                    mma16816(c, ph, vl4 + 2 * q);
                    mma16816(c, pl, vh4 + 2 * q);
                }
            }
        }
        __syncthreads();
    }

    // ---- normalize + write ctx as bf16 hi/lo ----
    float inv0 = 1.f / ls0, inv1 = 1.f / ls1;
#pragma unroll
    for (int nd = 0; nd < 8; nd++) {
        int c0 = gcol + nd * 8 + (lane & 3) * 2;
#pragma unroll
        for (int hr = 0; hr < 2; hr++) {
            size_t row = gq0 + wid * 16 + (lane >> 2) + hr * 8;
            float inv = hr ? inv1 : inv0;
            float v0 = oacc[nd][hr * 2 + 0] * inv;
            float v1 = oacc[nd][hr * 2 + 1] * inv;
            uint32_t hp, lp;
            split_pair(v0, v1, hp, lp);
            *(uint32_t*)(Ch + row * DM + c0) = hp;
            *(uint32_t*)(Cl + row * DM + c0) = lp;
        }
    }
}

// ---------------------------------------------------------------------------
// LayerNorm over last dim (1024). One block per row.
// ---------------------------------------------------------------------------
__global__ __launch_bounds__(256)
void ln_kernel(const float* __restrict__ H, const float* __restrict__ gamma,
               const float* __restrict__ beta, float* __restrict__ O)
{
    __shared__ float red[16];
    const int r = blockIdx.x;
    const int tid = threadIdx.x;
    const float* h = H + (size_t)r * DM;

    float4 v = *(const float4*)(h + tid * 4);
    float sum = v.x + v.y + v.z + v.w;
    float sq  = v.x * v.x + v.y * v.y + v.z * v.z + v.w * v.w;
#pragma unroll
    for (int o = 16; o > 0; o >>= 1) {
        sum += __shfl_xor_sync(0xffffffffu, sum, o);
        sq  += __shfl_xor_sync(0xffffffffu, sq,  o);
    }
    int wd = tid >> 5;
    if ((tid & 31) == 0) { red[wd] = sum; red[8 + wd] = sq; }
    __syncthreads();
    if (tid < 32) {
        float s2 = (tid < 8) ? red[tid]     : 0.f;
        float q2 = (tid < 8) ? red[8 + tid] : 0.f;
#pragma unroll
        for (int o = 4; o > 0; o >>= 1) {
            s2 += __shfl_xor_sync(0xffffffffu, s2, o);
            q2 += __shfl_xor_sync(0xffffffffu, q2, o);
        }
        if (tid == 0) { red[0] = s2; red[1] = q2; }
    }
    __syncthreads();
    float mu   = red[0] * (1.f / 1024.f);
    float var  = red[1] * (1.f / 1024.f) - mu * mu;
    float rstd = rsqrtf(var + 1e-12f);

    float4 g = *(const float4*)(gamma + tid * 4);
    float4 t = *(const float4*)(beta  + tid * 4);
    float4 o;
    o.x = (v.x - mu) * rstd * g.x + t.x;
    o.y = (v.y - mu) * rstd * g.y + t.y;
    o.z = (v.z - mu) * rstd * g.z + t.z;
    o.w = (v.w - mu) * rstd * g.w + t.w;
    *(float4*)(O + (size_t)r * DM + tid * 4) = o;
}

// ---------------------------------------------------------------------------
extern "C" void kernel_launch(void* const* d_in, const int* in_sizes, int n_in,
                              void* d_out, int out_size)
{
    const float* X     = (const float*)d_in[0];
    const float* Wq    = (const float*)d_in[1];
    const float* bq    = (const float*)d_in[2];
    const float* Wk    = (const float*)d_in[3];
    const float* bk    = (const float*)d_in[4];
    const float* Wv    = (const float*)d_in[5];
    const float* bv    = (const float*)d_in[6];
    const float* Wo    = (const float*)d_in[7];
    const float* bo    = (const float*)d_in[8];
    const float* gamma = (const float*)d_in[9];
    const float* beta  = (const float*)d_in[10];
    float* out = (float*)d_out;

    bf16 *Qh, *Ql, *Kh, *Kl, *Vh, *Vl, *Ch, *Cl, *Xh, *Xl, *Wth, *Wtl;
    float* Hp;
    cudaGetSymbolAddress((void**)&Qh, g_Qh);
    cudaGetSymbolAddress((void**)&Ql, g_Ql);
    cudaGetSymbolAddress((void**)&Kh, g_Kh);
    cudaGetSymbolAddress((void**)&Kl, g_Kl);
    cudaGetSymbolAddress((void**)&Vh, g_Vh);
    cudaGetSymbolAddress((void**)&Vl, g_Vl);
    cudaGetSymbolAddress((void**)&Ch, g_Ch);
    cudaGetSymbolAddress((void**)&Cl, g_Cl);
    cudaGetSymbolAddress((void**)&Xh, g_Xh);
    cudaGetSymbolAddress((void**)&Xl, g_Xl);
    cudaGetSymbolAddress((void**)&Wth, g_Wth);
    cudaGetSymbolAddress((void**)&Wtl, g_Wtl);
    cudaGetSymbolAddress((void**)&Hp, g_H);

    dim3 tb(32, 8), tg(DM / 32, DM / 32);
    transpose_split_kernel<<<tg, tb>>>(Wq, Wth + 0 * DM * DM, Wtl + 0 * DM * DM);
    transpose_split_kernel<<<tg, tb>>>(Wk, Wth + 1 * DM * DM, Wtl + 1 * DM * DM);
    transpose_split_kernel<<<tg, tb>>>(Wv, Wth + 2 * DM * DM, Wtl + 2 * DM * DM);
    transpose_split_kernel<<<tg, tb>>>(Wo, Wth + 3 * DM * DM, Wtl + 3 * DM * DM);

    split_kernel<<<MTOT * DM / 1024, 256>>>(X, Xh, Xl);

    cudaFuncSetAttribute(gemm_mma, cudaFuncAttributeMaxDynamicSharedMemorySize,
                         GSMEM);
    cudaFuncSetAttribute(attn_mma, cudaFuncAttributeMaxDynamicSharedMemorySize,
                         ASMEM);

    const float qscale = 0.125f * 1.4426950408889634f;  // 1/sqrt(Dh) * log2(e)
    dim3 gg(DM / 128, MTOT / 128);
    gemm_mma<<<gg, 256, GSMEM>>>(Xh, Xl, Wth + 0 * DM * DM, Wtl + 0 * DM * DM,
                                 bq, nullptr, nullptr, Qh, Ql, qscale);
    gemm_mma<<<gg, 256, GSMEM>>>(Xh, Xl, Wth + 1 * DM * DM, Wtl + 1 * DM * DM,
                                 bk, nullptr, nullptr, Kh, Kl, 1.0f);
    gemm_mma<<<gg, 256, GSMEM>>>(Xh, Xl, Wth + 2 * DM * DM, Wtl + 2 * DM * DM,
                                 bv, nullptr, nullptr, Vh, Vl, 1.0f);

    dim3 ga(SLEN / 128, NHEAD, 2);
    attn_mma<<<ga, 256, ASMEM>>>(Qh, Ql, Kh, Kl, Vh, Vl, Ch, Cl);

    gemm_mma<<<gg, 256, GSMEM>>>(Ch, Cl, Wth + 3 * DM * DM, Wtl + 3 * DM * DM,
                                 bo, X, Hp, nullptr, nullptr, 1.0f);

    ln_kernel<<<MTOT, 256>>>(Hp, gamma, beta, out);
}

// round 6
// speedup vs baseline: 4.5544x; 1.0918x over previous
#include <cuda_runtime.h>
#include <cuda_bf16.h>
#include <cstdint>

#define MTOT 4096          // B*S
#define DM   1024
#define SLEN 2048
#define NHEAD 16
#define DHEAD 64

typedef __nv_bfloat16 bf16;

// ---------------- scratch ---------------------------------------------------
__device__ bf16 g_Qh[MTOT * DM], g_Ql[MTOT * DM];
__device__ bf16 g_Kh[MTOT * DM], g_Kl[MTOT * DM];
__device__ bf16 g_Vh[MTOT * DM], g_Vl[MTOT * DM];
__device__ bf16 g_Ch[MTOT * DM], g_Cl[MTOT * DM];
__device__ bf16 g_Xh[MTOT * DM], g_Xl[MTOT * DM];
__device__ bf16 g_Wth[4][DM * DM], g_Wtl[4][DM * DM];  // [0..2]=QKV packed, [3]=O
__device__ float g_H[MTOT * DM];

// ---------------- helpers ---------------------------------------------------
__device__ __forceinline__ uint32_t smem_u32(const void* p) {
    uint32_t a;
    asm("{ .reg .u64 t; cvta.to.shared.u64 t, %1; cvt.u32.u64 %0, t; }"
        : "=r"(a) : "l"(p));
    return a;
}
__device__ __forceinline__ void cp16(uint32_t dst, const void* src) {
    asm volatile("cp.async.cg.shared.global [%0], [%1], 16;"
                 :: "r"(dst), "l"(src) : "memory");
}
#define CP_COMMIT() asm volatile("cp.async.commit_group;" ::: "memory")
#define CP_WAIT(n)  asm volatile("cp.async.wait_group %0;" :: "n"(n) : "memory")

__device__ __forceinline__ void ldsm4(uint32_t* r, uint32_t a) {
    asm volatile("ldmatrix.sync.aligned.m8n8.x4.shared.b16 {%0,%1,%2,%3}, [%4];"
                 : "=r"(r[0]), "=r"(r[1]), "=r"(r[2]), "=r"(r[3]) : "r"(a));
}
__device__ __forceinline__ void ldsm4t(uint32_t* r, uint32_t a) {
    asm volatile("ldmatrix.sync.aligned.m8n8.x4.trans.shared.b16 {%0,%1,%2,%3}, [%4];"
                 : "=r"(r[0]), "=r"(r[1]), "=r"(r[2]), "=r"(r[3]) : "r"(a));
}
__device__ __forceinline__ void mma16816(float* c, const uint32_t* a,
                                         const uint32_t* b) {
    asm volatile(
        "mma.sync.aligned.m16n8k16.row.col.f32.bf16.bf16.f32 "
        "{%0,%1,%2,%3}, {%4,%5,%6,%7}, {%8,%9}, {%0,%1,%2,%3};"
        : "+f"(c[0]), "+f"(c[1]), "+f"(c[2]), "+f"(c[3])
        : "r"(a[0]), "r"(a[1]), "r"(a[2]), "r"(a[3]), "r"(b[0]), "r"(b[1]));
}
__device__ __forceinline__ void split_pair(float v0, float v1,
                                           uint32_t& hi, uint32_t& lo) {
    uint32_t h;
    asm("cvt.rn.bf16x2.f32 %0, %1, %2;" : "=r"(h) : "f"(v1), "f"(v0));
    __nv_bfloat162 hb = *reinterpret_cast<__nv_bfloat162*>(&h);
    float r0 = __low2float(hb), r1 = __high2float(hb);
    uint32_t l;
    asm("cvt.rn.bf16x2.f32 %0, %1, %2;" : "=r"(l) : "f"(v1 - r1), "f"(v0 - r0));
    hi = h; lo = l;
}

// ---------------------------------------------------------------------------
// split: fp32 -> (hi, lo) bf16
// ---------------------------------------------------------------------------
__global__ __launch_bounds__(256)
void split_kernel(const float* __restrict__ X, bf16* __restrict__ H,
                  bf16* __restrict__ L)
{
    int i = (blockIdx.x * 256 + threadIdx.x) * 4;
    float4 v = *(const float4*)(X + i);
    uint32_t h0, l0, h1, l1;
    split_pair(v.x, v.y, h0, l0);
    split_pair(v.z, v.w, h1, l1);
    *(uint32_t*)(H + i)     = h0;
    *(uint32_t*)(H + i + 2) = h1;
    *(uint32_t*)(L + i)     = l0;
    *(uint32_t*)(L + i + 2) = l1;
}

// ---------------------------------------------------------------------------
// transpose + split all 4 weights in one launch (grid.z selects)
// ---------------------------------------------------------------------------
__global__ __launch_bounds__(256)
void transpose_split_kernel(const float* __restrict__ W0,
                            const float* __restrict__ W1,
                            const float* __restrict__ W2,
                            const float* __restrict__ W3,
                            bf16* __restrict__ ThBase,
                            bf16* __restrict__ TlBase)
{
    __shared__ float t[32][33];
    const int z = blockIdx.z;
    const float* W = (z == 0) ? W0 : (z == 1) ? W1 : (z == 2) ? W2 : W3;
    bf16* Th = ThBase + (size_t)z * DM * DM;
    bf16* Tl = TlBase + (size_t)z * DM * DM;
    int n0 = blockIdx.x * 32, k0 = blockIdx.y * 32;
    int tx = threadIdx.x, ty = threadIdx.y;   // 32 x 8
#pragma unroll
    for (int j = 0; j < 4; j++)
        t[ty + j * 8][tx] = W[(size_t)(k0 + ty + j * 8) * DM + n0 + tx];
    __syncthreads();
#pragma unroll
    for (int j = 0; j < 4; j++) {
        float v = t[tx][ty + j * 8];
        bf16 h = __float2bfloat16(v);
        size_t o = (size_t)(n0 + ty + j * 8) * DM + k0 + tx;
        Th[o] = h;
        Tl[o] = __float2bfloat16(v - __bfloat162float(h));
    }
}

// ---------------------------------------------------------------------------
// GEMM core (128x128 CTA tile, BK=32, 8 warps). Shared by both GEMM kernels.
// ---------------------------------------------------------------------------
#define GROWB 80
#define GTILE (128 * GROWB)       // 10240
#define GSTG  (4 * GTILE)         // 40960
#define GSMEM (2 * GSTG)          // 81920

struct GemmAcc { float a[2][8][4]; };

__device__ __forceinline__ void gemm_core(
    const bf16* Ah, const bf16* Al, const bf16* BhRow, const bf16* BlRow,
    int m0, uint32_t sb, int tid, int lane, int wm, int wn, GemmAcc& G)
{
#pragma unroll
    for (int mt = 0; mt < 2; mt++)
#pragma unroll
        for (int nt = 0; nt < 8; nt++)
#pragma unroll
            for (int e = 0; e < 4; e++) G.a[mt][nt][e] = 0.f;

    const bf16* srcs[4] = {Ah, Al, BhRow, BlRow};

    auto load = [&](int ki, int st) {
        const int k0 = ki * 32;
#pragma unroll
        for (int t = 0; t < 4; t++) {
            const int rb = (t < 2) ? m0 : 0;
            const bf16* s = srcs[t];
#pragma unroll
            for (int i = 0; i < 2; i++) {
                int idx = tid + i * 256;
                int row = idx >> 2, slot = idx & 3;
                cp16(sb + st * GSTG + t * GTILE + row * GROWB + slot * 16,
                     s + (size_t)(rb + row) * DM + k0 + slot * 8);
            }
        }
    };

    load(0, 0); CP_COMMIT();

    for (int ki = 0; ki < 32; ki++) {
        const int st = ki & 1;
        if (ki < 31) { load(ki + 1, st ^ 1); CP_COMMIT(); CP_WAIT(1); }
        else         { CP_WAIT(0); }
        __syncthreads();
        const uint32_t base = sb + st * GSTG;
#pragma unroll
        for (int ks = 0; ks < 2; ks++) {
            uint32_t ah[2][4], al[2][4];
#pragma unroll
            for (int mt = 0; mt < 2; mt++) {
                uint32_t r = wm * 32 + mt * 16 + (lane & 15);
                uint32_t cb = (ks * 16 + (lane >> 4) * 8) * 2;
                ldsm4(ah[mt], base + r * GROWB + cb);
                ldsm4(al[mt], base + GTILE + r * GROWB + cb);
            }
#pragma unroll
            for (int p = 0; p < 4; p++) {
                uint32_t r = wn * 64 + p * 16 + ((lane >> 4) & 1) * 8 + (lane & 7);
                uint32_t cb = (ks * 16 + ((lane >> 3) & 1) * 8) * 2;
                uint32_t bh[4], bl[4];
                ldsm4(bh, base + 2 * GTILE + r * GROWB + cb);
                ldsm4(bl, base + 3 * GTILE + r * GROWB + cb);
#pragma unroll
                for (int mt = 0; mt < 2; mt++) {
#pragma unroll
                    for (int q = 0; q < 2; q++) {
                        float* c = G.a[mt][2 * p + q];
                        mma16816(c, ah[mt], bh + 2 * q);
                        mma16816(c, ah[mt], bl + 2 * q);
                        mma16816(c, al[mt], bh + 2 * q);
                    }
                }
            }
        }
        __syncthreads();
    }
}

// Fused QKV GEMM: grid.x = 3072/128 = 24, grid.y = 32. Epilogue -> bf16 hi/lo.
__global__ __launch_bounds__(256, 2)
void qkv_gemm(const bf16* __restrict__ Ah, const bf16* __restrict__ Al,
              const bf16* __restrict__ WthPacked, const bf16* __restrict__ WtlPacked,
              const float* __restrict__ bq, const float* __restrict__ bk,
              const float* __restrict__ bv,
              bf16* __restrict__ Qh, bf16* __restrict__ Ql,
              bf16* __restrict__ Kh, bf16* __restrict__ Kl,
              bf16* __restrict__ Vh, bf16* __restrict__ Vl, float qscale)
{
    extern __shared__ __align__(16) char smraw[];
    const uint32_t sb = smem_u32(smraw);
    const int tid = threadIdx.x;
    const int lane = tid & 31, wid = tid >> 5;
    const int wm = wid >> 1, wn = wid & 1;
    const int m0 = blockIdx.y * 128, n0 = blockIdx.x * 128;
    const int mat = n0 >> 10;                 // 0=Q,1=K,2=V
    const int nc0 = n0 & 1023;

    GemmAcc G;
    gemm_core(Ah, Al, WthPacked + (size_t)n0 * DM, WtlPacked + (size_t)n0 * DM,
              m0, sb, tid, lane, wm, wn, G);

    const float* bias = (mat == 0) ? bq : (mat == 1) ? bk : bv;
    bf16* Oh = (mat == 0) ? Qh : (mat == 1) ? Kh : Vh;
    bf16* Ol = (mat == 0) ? Ql : (mat == 1) ? Kl : Vl;
    const float scale = (mat == 0) ? qscale : 1.0f;

#pragma unroll
    for (int mt = 0; mt < 2; mt++) {
        int r0 = m0 + wm * 32 + mt * 16 + (lane >> 2);
#pragma unroll
        for (int nt = 0; nt < 8; nt++) {
            int c0 = nc0 + wn * 64 + nt * 8 + (lane & 3) * 2;
            float b0 = bias[c0], b1 = bias[c0 + 1];
#pragma unroll
            for (int hr = 0; hr < 2; hr++) {
                int rr = r0 + hr * 8;
                float v0 = (G.a[mt][nt][hr * 2 + 0] + b0) * scale;
                float v1 = (G.a[mt][nt][hr * 2 + 1] + b1) * scale;
                size_t off = (size_t)rr * DM + c0;
                uint32_t hp, lp;
                split_pair(v0, v1, hp, lp);
                *(uint32_t*)(Oh + off) = hp;
                *(uint32_t*)(Ol + off) = lp;
            }
        }
    }
}

// O-proj GEMM: fp32 out, + bias + residual.
__global__ __launch_bounds__(256, 2)
void oproj_gemm(const bf16* __restrict__ Ah, const bf16* __restrict__ Al,
                const bf16* __restrict__ Bh, const bf16* __restrict__ Bl,
                const float* __restrict__ bias, const float* __restrict__ res,
                float* __restrict__ Cf)
{
    extern __shared__ __align__(16) char smraw[];
    const uint32_t sb = smem_u32(smraw);
    const int tid = threadIdx.x;
    const int lane = tid & 31, wid = tid >> 5;
    const int wm = wid >> 1, wn = wid & 1;
    const int m0 = blockIdx.y * 128, n0 = blockIdx.x * 128;

    GemmAcc G;
    gemm_core(Ah, Al, Bh + (size_t)n0 * DM, Bl + (size_t)n0 * DM,
              m0, sb, tid, lane, wm, wn, G);

#pragma unroll
    for (int mt = 0; mt < 2; mt++) {
        int r0 = m0 + wm * 32 + mt * 16 + (lane >> 2);
#pragma unroll
        for (int nt = 0; nt < 8; nt++) {
            int c0 = n0 + wn * 64 + nt * 8 + (lane & 3) * 2;
            float b0 = bias[c0], b1 = bias[c0 + 1];
#pragma unroll
            for (int hr = 0; hr < 2; hr++) {
                int rr = r0 + hr * 8;
                size_t off = (size_t)rr * DM + c0;
                float2 rv = *(const float2*)(res + off);
                float2 o;
                o.x = G.a[mt][nt][hr * 2 + 0] + b0 + rv.x;
                o.y = G.a[mt][nt][hr * 2 + 1] + b1 + rv.y;
                *(float2*)(Cf + off) = o;
            }
        }
    }
}

// ---------------------------------------------------------------------------
// Tensor-core flash attention. 128 threads / 4 warps / 64 q-rows per CTA.
// Grid (SLEN/64, NHEAD, B) = 1024 CTAs, target occupancy 3.
// ---------------------------------------------------------------------------
#define AROWB 144
#define ATILE (64 * AROWB)        // 9216
#define ASTG  (4 * ATILE)         // 36864
#define ASMEM (2 * ASTG)          // 73728

__global__ __launch_bounds__(128, 3)
void attn_mma(const bf16* __restrict__ Qh, const bf16* __restrict__ Ql,
              const bf16* __restrict__ Kh, const bf16* __restrict__ Kl,
              const bf16* __restrict__ Vh, const bf16* __restrict__ Vl,
              bf16* __restrict__ Ch, bf16* __restrict__ Cl)
{
    extern __shared__ __align__(16) char smraw[];
    const uint32_t sb = smem_u32(smraw);
    const int tid = threadIdx.x;
    const int lane = tid & 31, wid = tid >> 5;      // 4 warps
    const int qt = blockIdx.x, hd = blockIdx.y, bb = blockIdx.z;
    const size_t gq0 = (size_t)bb * SLEN + qt * 64;
    const size_t gk0 = (size_t)bb * SLEN;
    const int gcol = hd * DHEAD;

    // ---- stage Q (hi @ sb, lo @ sb+ATILE; consumed before KV stage 0) ----
#pragma unroll
    for (int i = 0; i < 8; i++) {
        int idx = tid + i * 128;              // 0..1023
        int t = idx >> 9;                     // 0 hi, 1 lo
        int rr = (idx >> 3) & 63;
        int ch = idx & 7;
        const bf16* s = t ? Ql : Qh;
        cp16(sb + t * ATILE + rr * AROWB + ch * 16,
             s + (gq0 + rr) * DM + gcol + ch * 8);
    }
    CP_COMMIT(); CP_WAIT(0);
    __syncthreads();

    uint32_t qfh[4][4], qfl[4][4];
#pragma unroll
    for (int ks = 0; ks < 4; ks++) {
        uint32_t r = wid * 16 + (lane & 15);
        uint32_t cb = (ks * 16 + (lane >> 4) * 8) * 2;
        ldsm4(qfh[ks], sb + r * AROWB + cb);
        ldsm4(qfl[ks], sb + ATILE + r * AROWB + cb);
    }
    __syncthreads();

    float oacc[8][4];
#pragma unroll
    for (int nd = 0; nd < 8; nd++)
#pragma unroll
        for (int e = 0; e < 4; e++) oacc[nd][e] = 0.f;
    float mx0 = -1e30f, mx1 = -1e30f, ls0 = 0.f, ls1 = 0.f;

    const bf16* kvsrc[4] = {Kh, Kl, Vh, Vl};
    auto loadkv = [&](int ti, int st) {
        const int t0 = ti * 64;
#pragma unroll
        for (int i = 0; i < 16; i++) {
            int idx = tid + i * 128;          // 0..2047
            int t = idx >> 9;
            int rr = (idx >> 3) & 63;
            int ch = idx & 7;
            cp16(sb + st * ASTG + t * ATILE + rr * AROWB + ch * 16,
                 kvsrc[t] + (gk0 + t0 + rr) * DM + gcol + ch * 8);
        }
    };

    loadkv(0, 0); CP_COMMIT();

    for (int ti = 0; ti < 32; ti++) {
        const int st = ti & 1;
        if (ti < 31) { loadkv(ti + 1, st ^ 1); CP_COMMIT(); CP_WAIT(1); }
        else         { CP_WAIT(0); }
        __syncthreads();
        const uint32_t kb = sb + st * ASTG;

        // ---- S = Q K^T ----
        float sacc[8][4];
#pragma unroll
        for (int nt = 0; nt < 8; nt++)
#pragma unroll
            for (int e = 0; e < 4; e++) sacc[nt][e] = 0.f;
#pragma unroll
        for (int ks = 0; ks < 4; ks++) {
#pragma unroll
            for (int p = 0; p < 4; p++) {
                uint32_t r = p * 16 + ((lane >> 4) & 1) * 8 + (lane & 7);
                uint32_t cb = (ks * 16 + ((lane >> 3) & 1) * 8) * 2;
                uint32_t kh4[4], kl4[4];
                ldsm4(kh4, kb + r * AROWB + cb);
                ldsm4(kl4, kb + ATILE + r * AROWB + cb);
#pragma unroll
                for (int q = 0; q < 2; q++) {
                    float* c = sacc[2 * p + q];
                    mma16816(c, qfh[ks], kh4 + 2 * q);
                    mma16816(c, qfh[ks], kl4 + 2 * q);
                    mma16816(c, qfl[ks], kh4 + 2 * q);
                }
            }
        }

        // ---- online softmax ----
        float t0 = -1e30f, t1 = -1e30f;
#pragma unroll
        for (int nt = 0; nt < 8; nt++) {
            t0 = fmaxf(t0, fmaxf(sacc[nt][0], sacc[nt][1]));
            t1 = fmaxf(t1, fmaxf(sacc[nt][2], sacc[nt][3]));
        }
        t0 = fmaxf(t0, __shfl_xor_sync(0xffffffffu, t0, 1));
        t0 = fmaxf(t0, __shfl_xor_sync(0xffffffffu, t0, 2));
        t1 = fmaxf(t1, __shfl_xor_sync(0xffffffffu, t1, 1));
        t1 = fmaxf(t1, __shfl_xor_sync(0xffffffffu, t1, 2));
        float mn0 = fmaxf(mx0, t0), mn1 = fmaxf(mx1, t1);
        float cr0 = exp2f(mx0 - mn0), cr1 = exp2f(mx1 - mn1);
        mx0 = mn0; mx1 = mn1;

        float ps0 = 0.f, ps1 = 0.f;
#pragma unroll
        for (int nt = 0; nt < 8; nt++) {
            sacc[nt][0] = exp2f(sacc[nt][0] - mn0); ps0 += sacc[nt][0];
            sacc[nt][1] = exp2f(sacc[nt][1] - mn0); ps0 += sacc[nt][1];
            sacc[nt][2] = exp2f(sacc[nt][2] - mn1); ps1 += sacc[nt][2];
            sacc[nt][3] = exp2f(sacc[nt][3] - mn1); ps1 += sacc[nt][3];
        }
        ps0 += __shfl_xor_sync(0xffffffffu, ps0, 1);
        ps0 += __shfl_xor_sync(0xffffffffu, ps0, 2);
        ps1 += __shfl_xor_sync(0xffffffffu, ps1, 1);
        ps1 += __shfl_xor_sync(0xffffffffu, ps1, 2);
        ls0 = ls0 * cr0 + ps0;
        ls1 = ls1 * cr1 + ps1;
#pragma unroll
        for (int nd = 0; nd < 8; nd++) {
            oacc[nd][0] *= cr0; oacc[nd][1] *= cr0;
            oacc[nd][2] *= cr1; oacc[nd][3] *= cr1;
        }

        // ---- ctx += P V ----
        const uint32_t vb = kb + 2 * ATILE;
#pragma unroll
        for (int kt = 0; kt < 4; kt++) {
            uint32_t ph[4], pl[4];
            split_pair(sacc[2 * kt][0],     sacc[2 * kt][1],     ph[0], pl[0]);
            split_pair(sacc[2 * kt][2],     sacc[2 * kt][3],     ph[1], pl[1]);
            split_pair(sacc[2 * kt + 1][0], sacc[2 * kt + 1][1], ph[2], pl[2]);
            split_pair(sacc[2 * kt + 1][2], sacc[2 * kt + 1][3], ph[3], pl[3]);
#pragma unroll
            for (int pd = 0; pd < 4; pd++) {
                uint32_t r = kt * 16 + (lane & 15);
                uint32_t cb = (pd * 16 + (lane >> 4) * 8) * 2;
                uint32_t vh4[4], vl4[4];
                ldsm4t(vh4, vb + r * AROWB + cb);
                ldsm4t(vl4, vb + ATILE + r * AROWB + cb);
#pragma unroll
                for (int q = 0; q < 2; q++) {
                    float* c = oacc[2 * pd + q];
                    mma16816(c, ph, vh4 + 2 * q);
                    mma16816(c, ph, vl4 + 2 * q);
                    mma16816(c, pl, vh4 + 2 * q);
                }
            }
        }
        __syncthreads();
    }

    // ---- normalize + write ctx as bf16 hi/lo ----
    float inv0 = 1.f / ls0, inv1 = 1.f / ls1;
#pragma unroll
    for (int nd = 0; nd < 8; nd++) {
        int c0 = gcol + nd * 8 + (lane & 3) * 2;
#pragma unroll
        for (int hr = 0; hr < 2; hr++) {
            size_t row = gq0 + wid * 16 + (lane >> 2) + hr * 8;
            float inv = hr ? inv1 : inv0;
            float v0 = oacc[nd][hr * 2 + 0] * inv;
            float v1 = oacc[nd][hr * 2 + 1] * inv;
            uint32_t hp, lp;
            split_pair(v0, v1, hp, lp);
            *(uint32_t*)(Ch + row * DM + c0) = hp;
            *(uint32_t*)(Cl + row * DM + c0) = lp;
        }
    }
}

// ---------------------------------------------------------------------------
// LayerNorm over last dim (1024). One block per row.
// ---------------------------------------------------------------------------
__global__ __launch_bounds__(256)
void ln_kernel(const float* __restrict__ H, const float* __restrict__ gamma,
               const float* __restrict__ beta, float* __restrict__ O)
{
    __shared__ float red[16];
    const int r = blockIdx.x;
    const int tid = threadIdx.x;
    const float* h = H + (size_t)r * DM;

    float4 v = *(const float4*)(h + tid * 4);
    float sum = v.x + v.y + v.z + v.w;
    float sq  = v.x * v.x + v.y * v.y + v.z * v.z + v.w * v.w;
#pragma unroll
    for (int o = 16; o > 0; o >>= 1) {
        sum += __shfl_xor_sync(0xffffffffu, sum, o);
        sq  += __shfl_xor_sync(0xffffffffu, sq,  o);
    }
    int wd = tid >> 5;
    if ((tid & 31) == 0) { red[wd] = sum; red[8 + wd] = sq; }
    __syncthreads();
    if (tid < 32) {
        float s2 = (tid < 8) ? red[tid]     : 0.f;
        float q2 = (tid < 8) ? red[8 + tid] : 0.f;
#pragma unroll
        for (int o = 4; o > 0; o >>= 1) {
            s2 += __shfl_xor_sync(0xffffffffu, s2, o);
            q2 += __shfl_xor_sync(0xffffffffu, q2, o);
        }
        if (tid == 0) { red[0] = s2; red[1] = q2; }
    }
    __syncthreads();
    float mu   = red[0] * (1.f / 1024.f);
    float var  = red[1] * (1.f / 1024.f) - mu * mu;
    float rstd = rsqrtf(var + 1e-12f);

    float4 g = *(const float4*)(gamma + tid * 4);
    float4 t = *(const float4*)(beta  + tid * 4);
    float4 o;
    o.x = (v.x - mu) * rstd * g.x + t.x;
    o.y = (v.y - mu) * rstd * g.y + t.y;
    o.z = (v.z - mu) * rstd * g.z + t.z;
    o.w = (v.w - mu) * rstd * g.w + t.w;
    *(float4*)(O + (size_t)r * DM + tid * 4) = o;
}

// ---------------------------------------------------------------------------
extern "C" void kernel_launch(void* const* d_in, const int* in_sizes, int n_in,
                              void* d_out, int out_size)
{
    const float* X     = (const float*)d_in[0];
    const float* Wq    = (const float*)d_in[1];
    const float* bq    = (const float*)d_in[2];
    const float* Wk    = (const float*)d_in[3];
    const float* bk    = (const float*)d_in[4];
    const float* Wv    = (const float*)d_in[5];
    const float* bv    = (const float*)d_in[6];
    const float* Wo    = (const float*)d_in[7];
    const float* bo    = (const float*)d_in[8];
    const float* gamma = (const float*)d_in[9];
    const float* beta  = (const float*)d_in[10];
    float* out = (float*)d_out;

    bf16 *Qh, *Ql, *Kh, *Kl, *Vh, *Vl, *Ch, *Cl, *Xh, *Xl, *Wth, *Wtl;
    float* Hp;
    cudaGetSymbolAddress((void**)&Qh, g_Qh);
    cudaGetSymbolAddress((void**)&Ql, g_Ql);
    cudaGetSymbolAddress((void**)&Kh, g_Kh);
    cudaGetSymbolAddress((void**)&Kl, g_Kl);
    cudaGetSymbolAddress((void**)&Vh, g_Vh);
    cudaGetSymbolAddress((void**)&Vl, g_Vl);
    cudaGetSymbolAddress((void**)&Ch, g_Ch);
    cudaGetSymbolAddress((void**)&Cl, g_Cl);
    cudaGetSymbolAddress((void**)&Xh, g_Xh);
    cudaGetSymbolAddress((void**)&Xl, g_Xl);
    cudaGetSymbolAddress((void**)&Wth, g_Wth);
    cudaGetSymbolAddress((void**)&Wtl, g_Wtl);
    cudaGetSymbolAddress((void**)&Hp, g_H);

    // all 4 weight transposes in one launch
    dim3 tb(32, 8), tg(DM / 32, DM / 32, 4);
    transpose_split_kernel<<<tg, tb>>>(Wq, Wk, Wv, Wo, Wth, Wtl);

    split_kernel<<<MTOT * DM / 1024, 256>>>(X, Xh, Xl);

    cudaFuncSetAttribute(qkv_gemm, cudaFuncAttributeMaxDynamicSharedMemorySize,
                         GSMEM);
    cudaFuncSetAttribute(oproj_gemm, cudaFuncAttributeMaxDynamicSharedMemorySize,
                         GSMEM);
    cudaFuncSetAttribute(attn_mma, cudaFuncAttributeMaxDynamicSharedMemorySize,
                         ASMEM);

    const float qscale = 0.125f * 1.4426950408889634f;

    // fused QKV: 24 x 32 = 768 CTAs
    dim3 gq(3 * DM / 128, MTOT / 128);
    qkv_gemm<<<gq, 256, GSMEM>>>(Xh, Xl, Wth, Wtl, bq, bk, bv,
                                 Qh, Ql, Kh, Kl, Vh, Vl, qscale);

    dim3 ga(SLEN / 64, NHEAD, 2);
    attn_mma<<<ga, 128, ASMEM>>>(Qh, Ql, Kh, Kl, Vh, Vl, Ch, Cl);

    dim3 go(DM / 128, MTOT / 128);
    oproj_gemm<<<go, 256, GSMEM>>>(Ch, Cl, Wth + 3 * (size_t)DM * DM,
                                   Wtl + 3 * (size_t)DM * DM, bo, X, Hp);

    ln_kernel<<<MTOT, 256>>>(Hp, gamma, beta, out);
}

// round 7
// speedup vs baseline: 11.0318x; 2.4222x over previous
#include <cuda_runtime.h>
#include <cuda_fp16.h>
#include <cstdint>

#define MTOT 4096          // B*S
#define DM   1024
#define SLEN 2048
#define NHEAD 16
#define DHEAD 64

typedef __half half_t;

// ---------------- scratch ---------------------------------------------------
__device__ half_t g_X16[MTOT * DM];
__device__ half_t g_Q16[MTOT * DM];
__device__ half_t g_K16[MTOT * DM];
__device__ half_t g_V16[MTOT * DM];
__device__ half_t g_C16[MTOT * DM];
__device__ half_t g_Wt16[4][DM * DM];   // W^T [N,K]: 0..2 QKV packed, 3 = O
__device__ float  g_H[MTOT * DM];

// ---------------- helpers ---------------------------------------------------
__device__ __forceinline__ uint32_t smem_u32(const void* p) {
    uint32_t a;
    asm("{ .reg .u64 t; cvta.to.shared.u64 t, %1; cvt.u32.u64 %0, t; }"
        : "=r"(a) : "l"(p));
    return a;
}
__device__ __forceinline__ void cp16(uint32_t dst, const void* src) {
    asm volatile("cp.async.cg.shared.global [%0], [%1], 16;"
                 :: "r"(dst), "l"(src) : "memory");
}
#define CP_COMMIT() asm volatile("cp.async.commit_group;" ::: "memory")
#define CP_WAIT0()  asm volatile("cp.async.wait_group 0;" ::: "memory")

__device__ __forceinline__ void ldsm4(uint32_t* r, uint32_t a) {
    asm volatile("ldmatrix.sync.aligned.m8n8.x4.shared.b16 {%0,%1,%2,%3}, [%4];"
                 : "=r"(r[0]), "=r"(r[1]), "=r"(r[2]), "=r"(r[3]) : "r"(a));
}
__device__ __forceinline__ void ldsm4t(uint32_t* r, uint32_t a) {
    asm volatile("ldmatrix.sync.aligned.m8n8.x4.trans.shared.b16 {%0,%1,%2,%3}, [%4];"
                 : "=r"(r[0]), "=r"(r[1]), "=r"(r[2]), "=r"(r[3]) : "r"(a));
}
__device__ __forceinline__ void mmaf16(float* c, const uint32_t* a,
                                       const uint32_t* b) {
    asm volatile(
        "mma.sync.aligned.m16n8k16.row.col.f32.f16.f16.f32 "
        "{%0,%1,%2,%3}, {%4,%5,%6,%7}, {%8,%9}, {%0,%1,%2,%3};"
        : "+f"(c[0]), "+f"(c[1]), "+f"(c[2]), "+f"(c[3])
        : "r"(a[0]), "r"(a[1]), "r"(a[2]), "r"(a[3]), "r"(b[0]), "r"(b[1]));
}
// pack v0 -> low half, v1 -> high half
__device__ __forceinline__ uint32_t pack_h2(float v0, float v1) {
    uint32_t h;
    asm("cvt.rn.f16x2.f32 %0, %1, %2;" : "=r"(h) : "f"(v1), "f"(v0));
    return h;
}

// ---------------------------------------------------------------------------
// fp32 -> fp16 convert
// ---------------------------------------------------------------------------
__global__ __launch_bounds__(256)
void convert_kernel(const float* __restrict__ X, half_t* __restrict__ O)
{
    int i = (blockIdx.x * 256 + threadIdx.x) * 4;
    float4 v = *(const float4*)(X + i);
    *(uint32_t*)(O + i)     = pack_h2(v.x, v.y);
    *(uint32_t*)(O + i + 2) = pack_h2(v.z, v.w);
}

// ---------------------------------------------------------------------------
// transpose + convert all 4 weights (grid.z selects): W [K,N] -> Wt fp16 [N,K]
// ---------------------------------------------------------------------------
__global__ __launch_bounds__(256)
void transpose_cvt_kernel(const float* __restrict__ W0,
                          const float* __restrict__ W1,
                          const float* __restrict__ W2,
                          const float* __restrict__ W3,
                          half_t* __restrict__ TBase)
{
    __shared__ float t[32][33];
    const int z = blockIdx.z;
    const float* W = (z == 0) ? W0 : (z == 1) ? W1 : (z == 2) ? W2 : W3;
    half_t* T = TBase + (size_t)z * DM * DM;
    int n0 = blockIdx.x * 32, k0 = blockIdx.y * 32;
    int tx = threadIdx.x, ty = threadIdx.y;   // 32 x 8
#pragma unroll
    for (int j = 0; j < 4; j++)
        t[ty + j * 8][tx] = W[(size_t)(k0 + ty + j * 8) * DM + n0 + tx];
    __syncthreads();
#pragma unroll
    for (int j = 0; j < 4; j++)
        T[(size_t)(n0 + ty + j * 8) * DM + k0 + tx] =
            __float2half_rn(t[tx][ty + j * 8]);
}

// ---------------------------------------------------------------------------
// fp16 GEMM core: 128x128 CTA tile, BK=64, 16 k-iters, 2-stage, 8 warps.
// Single __syncthreads per iteration.
// ---------------------------------------------------------------------------
#define GROW 144                  // 128 data bytes + 16 pad
#define GT   (128 * GROW)         // 18432
#define GSTG (2 * GT)             // 36864 (A tile + B tile)
#define GSMEM (2 * GSTG)          // 73728

struct GemmAcc { float a[2][8][4]; };

__device__ __forceinline__ void gemm_core(
    const half_t* A, const half_t* BRow, int m0,
    uint32_t sb, int tid, int lane, int wm, int wn, GemmAcc& G)
{
#pragma unroll
    for (int mt = 0; mt < 2; mt++)
#pragma unroll
        for (int nt = 0; nt < 8; nt++)
#pragma unroll
            for (int e = 0; e < 4; e++) G.a[mt][nt][e] = 0.f;

    auto load = [&](int ki, int st) {
        const int k0 = ki * 64;
#pragma unroll
        for (int i = 0; i < 4; i++) {
            int idx = tid + i * 256;          // 0..1023
            int row = idx >> 3, slot = idx & 7;
            cp16(sb + st * GSTG + row * GROW + slot * 16,
                 A + (size_t)(m0 + row) * DM + k0 + slot * 8);
            cp16(sb + st * GSTG + GT + row * GROW + slot * 16,
                 BRow + (size_t)row * DM + k0 + slot * 8);
        }
    };

    load(0, 0); CP_COMMIT();

    for (int ki = 0; ki < 16; ki++) {
        const int st = ki & 1;
        CP_WAIT0();
        __syncthreads();
        if (ki < 15) { load(ki + 1, st ^ 1); CP_COMMIT(); }
        const uint32_t base = sb + st * GSTG;
#pragma unroll
        for (int ks = 0; ks < 4; ks++) {
            uint32_t am[2][4];
#pragma unroll
            for (int mt = 0; mt < 2; mt++) {
                uint32_t r = wm * 32 + mt * 16 + (lane & 15);
                uint32_t cb = (ks * 16 + (lane >> 4) * 8) * 2;
                ldsm4(am[mt], base + r * GROW + cb);
            }
#pragma unroll
            for (int p = 0; p < 4; p++) {
                uint32_t r = wn * 64 + p * 16 + ((lane >> 4) & 1) * 8 + (lane & 7);
                uint32_t cb = (ks * 16 + ((lane >> 3) & 1) * 8) * 2;
                uint32_t bf[4];
                ldsm4(bf, base + GT + r * GROW + cb);
#pragma unroll
                for (int mt = 0; mt < 2; mt++) {
#pragma unroll
                    for (int q = 0; q < 2; q++)
                        mmaf16(G.a[mt][2 * p + q], am[mt], bf + 2 * q);
                }
            }
        }
    }
}

// Fused QKV GEMM: grid (24, 32). Epilogue -> fp16.
__global__ __launch_bounds__(256, 2)
void qkv_gemm(const half_t* __restrict__ A, const half_t* __restrict__ WtPacked,
              const float* __restrict__ bq, const float* __restrict__ bk,
              const float* __restrict__ bv,
              half_t* __restrict__ Q, half_t* __restrict__ K,
              half_t* __restrict__ V, float qscale)
{
    extern __shared__ __align__(16) char smraw[];
    const uint32_t sb = smem_u32(smraw);
    const int tid = threadIdx.x;
    const int lane = tid & 31, wid = tid >> 5;
    const int wm = wid >> 1, wn = wid & 1;
    const int m0 = blockIdx.y * 128, n0 = blockIdx.x * 128;
    const int mat = n0 >> 10;                 // 0=Q,1=K,2=V
    const int nc0 = n0 & 1023;

    GemmAcc G;
    gemm_core(A, WtPacked + (size_t)n0 * DM, m0, sb, tid, lane, wm, wn, G);

    const float* bias = (mat == 0) ? bq : (mat == 1) ? bk : bv;
    half_t* O = (mat == 0) ? Q : (mat == 1) ? K : V;
    const float scale = (mat == 0) ? qscale : 1.0f;

#pragma unroll
    for (int mt = 0; mt < 2; mt++) {
        int r0 = m0 + wm * 32 + mt * 16 + (lane >> 2);
#pragma unroll
        for (int nt = 0; nt < 8; nt++) {
            int c0 = nc0 + wn * 64 + nt * 8 + (lane & 3) * 2;
            float b0 = bias[c0], b1 = bias[c0 + 1];
#pragma unroll
            for (int hr = 0; hr < 2; hr++) {
                int rr = r0 + hr * 8;
                float v0 = (G.a[mt][nt][hr * 2 + 0] + b0) * scale;
                float v1 = (G.a[mt][nt][hr * 2 + 1] + b1) * scale;
                *(uint32_t*)(O + (size_t)rr * DM + c0) = pack_h2(v0, v1);
            }
        }
    }
}

// O-proj GEMM: fp32 out + bias + residual.
__global__ __launch_bounds__(256, 2)
void oproj_gemm(const half_t* __restrict__ A, const half_t* __restrict__ B,
                const float* __restrict__ bias, const float* __restrict__ res,
                float* __restrict__ Cf)
{
    extern __shared__ __align__(16) char smraw[];
    const uint32_t sb = smem_u32(smraw);
    const int tid = threadIdx.x;
    const int lane = tid & 31, wid = tid >> 5;
    const int wm = wid >> 1, wn = wid & 1;
    const int m0 = blockIdx.y * 128, n0 = blockIdx.x * 128;

    GemmAcc G;
    gemm_core(A, B + (size_t)n0 * DM, m0, sb, tid, lane, wm, wn, G);

#pragma unroll
    for (int mt = 0; mt < 2; mt++) {
        int r0 = m0 + wm * 32 + mt * 16 + (lane >> 2);
#pragma unroll
        for (int nt = 0; nt < 8; nt++) {
            int c0 = n0 + wn * 64 + nt * 8 + (lane & 3) * 2;
            float b0 = bias[c0], b1 = bias[c0 + 1];
#pragma unroll
            for (int hr = 0; hr < 2; hr++) {
                int rr = r0 + hr * 8;
                size_t off = (size_t)rr * DM + c0;
                float2 rv = *(const float2*)(res + off);
                float2 o;
                o.x = G.a[mt][nt][hr * 2 + 0] + b0 + rv.x;
                o.y = G.a[mt][nt][hr * 2 + 1] + b1 + rv.y;
                *(float2*)(Cf + off) = o;
            }
        }
    }
}

// ---------------------------------------------------------------------------
// fp16 flash attention. 128 threads / 4 warps / 64 q-rows. Grid 1024, occ 4.
// ---------------------------------------------------------------------------
#define AROW 144
#define ATILE (64 * AROW)         // 9216
#define ASTG  (2 * ATILE)         // 18432 (K tile + V tile)
#define ASMEM (2 * ASTG)          // 36864

__global__ __launch_bounds__(128, 4)
void attn_mma(const half_t* __restrict__ Q, const half_t* __restrict__ K,
              const half_t* __restrict__ V, half_t* __restrict__ C)
{
    extern __shared__ __align__(16) char smraw[];
    const uint32_t sb = smem_u32(smraw);
    const int tid = threadIdx.x;
    const int lane = tid & 31, wid = tid >> 5;      // 4 warps
    const int qt = blockIdx.x, hd = blockIdx.y, bb = blockIdx.z;
    const size_t gq0 = (size_t)bb * SLEN + qt * 64;
    const size_t gk0 = (size_t)bb * SLEN;
    const int gcol = hd * DHEAD;

    // ---- stage Q into stage-0 area, pull to regs ----
#pragma unroll
    for (int i = 0; i < 4; i++) {
        int idx = tid + i * 128;              // 0..511
        int rr = idx >> 3, ch = idx & 7;
        cp16(sb + rr * AROW + ch * 16, Q + (gq0 + rr) * DM + gcol + ch * 8);
    }
    CP_COMMIT(); CP_WAIT0();
    __syncthreads();

    uint32_t qf[4][4];
#pragma unroll
    for (int ks = 0; ks < 4; ks++) {
        uint32_t r = wid * 16 + (lane & 15);
        uint32_t cb = (ks * 16 + (lane >> 4) * 8) * 2;
        ldsm4(qf[ks], sb + r * AROW + cb);
    }
    __syncthreads();

    float oacc[8][4];
#pragma unroll
    for (int nd = 0; nd < 8; nd++)
#pragma unroll
        for (int e = 0; e < 4; e++) oacc[nd][e] = 0.f;
    float mx0 = -1e30f, mx1 = -1e30f, ls0 = 0.f, ls1 = 0.f;

    auto loadkv = [&](int ti, int st) {
        const int t0 = ti * 64;
#pragma unroll
        for (int i = 0; i < 8; i++) {
            int idx = tid + i * 128;          // 0..1023
            int t = idx >> 9;                 // 0 = K, 1 = V
            int rr = (idx >> 3) & 63;
            int ch = idx & 7;
            const half_t* s = t ? V : K;
            cp16(sb + st * ASTG + t * ATILE + rr * AROW + ch * 16,
                 s + (gk0 + t0 + rr) * DM + gcol + ch * 8);
        }
    };

    loadkv(0, 0); CP_COMMIT();

    for (int ti = 0; ti < 32; ti++) {
        const int st = ti & 1;
        CP_WAIT0();
        __syncthreads();
        if (ti < 31) { loadkv(ti + 1, st ^ 1); CP_COMMIT(); }
        const uint32_t kb = sb + st * ASTG;

        // ---- S = Q K^T ----
        float sacc[8][4];
#pragma unroll
        for (int nt = 0; nt < 8; nt++)
#pragma unroll
            for (int e = 0; e < 4; e++) sacc[nt][e] = 0.f;
#pragma unroll
        for (int ks = 0; ks < 4; ks++) {
#pragma unroll
            for (int p = 0; p < 4; p++) {
                uint32_t r = p * 16 + ((lane >> 4) & 1) * 8 + (lane & 7);
                uint32_t cb = (ks * 16 + ((lane >> 3) & 1) * 8) * 2;
                uint32_t kf[4];
                ldsm4(kf, kb + r * AROW + cb);
#pragma unroll
                for (int q = 0; q < 2; q++)
                    mmaf16(sacc[2 * p + q], qf[ks], kf + 2 * q);
            }
        }

        // ---- online softmax ----
        float t0 = -1e30f, t1 = -1e30f;
#pragma unroll
        for (int nt = 0; nt < 8; nt++) {
            t0 = fmaxf(t0, fmaxf(sacc[nt][0], sacc[nt][1]));
            t1 = fmaxf(t1, fmaxf(sacc[nt][2], sacc[nt][3]));
        }
        t0 = fmaxf(t0, __shfl_xor_sync(0xffffffffu, t0, 1));
        t0 = fmaxf(t0, __shfl_xor_sync(0xffffffffu, t0, 2));
        t1 = fmaxf(t1, __shfl_xor_sync(0xffffffffu, t1, 1));
        t1 = fmaxf(t1, __shfl_xor_sync(0xffffffffu, t1, 2));
        float mn0 = fmaxf(mx0, t0), mn1 = fmaxf(mx1, t1);
        float cr0 = exp2f(mx0 - mn0), cr1 = exp2f(mx1 - mn1);
        mx0 = mn0; mx1 = mn1;

        float ps0 = 0.f, ps1 = 0.f;
#pragma unroll
        for (int nt = 0; nt < 8; nt++) {
            sacc[nt][0] = exp2f(sacc[nt][0] - mn0); ps0 += sacc[nt][0];
            sacc[nt][1] = exp2f(sacc[nt][1] - mn0); ps0 += sacc[nt][1];
            sacc[nt][2] = exp2f(sacc[nt][2] - mn1); ps1 += sacc[nt][2];
            sacc[nt][3] = exp2f(sacc[nt][3] - mn1); ps1 += sacc[nt][3];
        }
        ps0 += __shfl_xor_sync(0xffffffffu, ps0, 1);
        ps0 += __shfl_xor_sync(0xffffffffu, ps0, 2);
        ps1 += __shfl_xor_sync(0xffffffffu, ps1, 1);
        ps1 += __shfl_xor_sync(0xffffffffu, ps1, 2);
        ls0 = ls0 * cr0 + ps0;
        ls1 = ls1 * cr1 + ps1;
#pragma unroll
        for (int nd = 0; nd < 8; nd++) {
            oacc[nd][0] *= cr0; oacc[nd][1] *= cr0;
            oacc[nd][2] *= cr1; oacc[nd][3] *= cr1;
        }

        // ---- ctx += P V ----
        const uint32_t vb = kb + ATILE;
#pragma unroll
        for (int kt = 0; kt < 4; kt++) {
            uint32_t ph[4];
            ph[0] = pack_h2(sacc[2 * kt][0],     sacc[2 * kt][1]);
            ph[1] = pack_h2(sacc[2 * kt][2],     sacc[2 * kt][3]);
            ph[2] = pack_h2(sacc[2 * kt + 1][0], sacc[2 * kt + 1][1]);
            ph[3] = pack_h2(sacc[2 * kt + 1][2], sacc[2 * kt + 1][3]);
#pragma unroll
            for (int pd = 0; pd < 4; pd++) {
                uint32_t r = kt * 16 + (lane & 15);
                uint32_t cb = (pd * 16 + (lane >> 4) * 8) * 2;
                uint32_t vf[4];
                ldsm4t(vf, vb + r * AROW + cb);
#pragma unroll
                for (int q = 0; q < 2; q++)
                    mmaf16(oacc[2 * pd + q], ph, vf + 2 * q);
            }
        }
    }

    // ---- normalize + write ctx fp16 ----
    float inv0 = 1.f / ls0, inv1 = 1.f / ls1;
#pragma unroll
    for (int nd = 0; nd < 8; nd++) {
        int c0 = gcol + nd * 8 + (lane & 3) * 2;
#pragma unroll
        for (int hr = 0; hr < 2; hr++) {
            size_t row = gq0 + wid * 16 + (lane >> 2) + hr * 8;
            float inv = hr ? inv1 : inv0;
            float v0 = oacc[nd][hr * 2 + 0] * inv;
            float v1 = oacc[nd][hr * 2 + 1] * inv;
            *(uint32_t*)(C + row * DM + c0) = pack_h2(v0, v1);
        }
    }
}

// ---------------------------------------------------------------------------
// LayerNorm over last dim (1024). One block per row.
// ---------------------------------------------------------------------------
__global__ __launch_bounds__(256)
void ln_kernel(const float* __restrict__ H, const float* __restrict__ gamma,
               const float* __restrict__ beta, float* __restrict__ O)
{
    __shared__ float red[16];
    const int r = blockIdx.x;
    const int tid = threadIdx.x;
    const float* h = H + (size_t)r * DM;

    float4 v = *(const float4*)(h + tid * 4);
    float sum = v.x + v.y + v.z + v.w;
    float sq  = v.x * v.x + v.y * v.y + v.z * v.z + v.w * v.w;
#pragma unroll
    for (int o = 16; o > 0; o >>= 1) {
        sum += __shfl_xor_sync(0xffffffffu, sum, o);
        sq  += __shfl_xor_sync(0xffffffffu, sq,  o);
    }
    int wd = tid >> 5;
    if ((tid & 31) == 0) { red[wd] = sum; red[8 + wd] = sq; }
    __syncthreads();
    if (tid < 32) {
        float s2 = (tid < 8) ? red[tid]     : 0.f;
        float q2 = (tid < 8) ? red[8 + tid] : 0.f;
#pragma unroll
        for (int o = 4; o > 0; o >>= 1) {
            s2 += __shfl_xor_sync(0xffffffffu, s2, o);
            q2 += __shfl_xor_sync(0xffffffffu, q2, o);
        }
        if (tid == 0) { red[0] = s2; red[1] = q2; }
    }
    __syncthreads();
    float mu   = red[0] * (1.f / 1024.f);
    float var  = red[1] * (1.f / 1024.f) - mu * mu;
    float rstd = rsqrtf(var + 1e-12f);

    float4 g = *(const float4*)(gamma + tid * 4);
    float4 t = *(const float4*)(beta  + tid * 4);
    float4 o;
    o.x = (v.x - mu) * rstd * g.x + t.x;
    o.y = (v.y - mu) * rstd * g.y + t.y;
    o.z = (v.z - mu) * rstd * g.z + t.z;
    o.w = (v.w - mu) * rstd * g.w + t.w;
    *(float4*)(O + (size_t)r * DM + tid * 4) = o;
}

// ---------------------------------------------------------------------------
extern "C" void kernel_launch(void* const* d_in, const int* in_sizes, int n_in,
                              void* d_out, int out_size)
{
    const float* X     = (const float*)d_in[0];
    const float* Wq    = (const float*)d_in[1];
    const float* bq    = (const float*)d_in[2];
    const float* Wk    = (const float*)d_in[3];
    const float* bk    = (const float*)d_in[4];
    const float* Wv    = (const float*)d_in[5];
    const float* bv    = (const float*)d_in[6];
    const float* Wo    = (const float*)d_in[7];
    const float* bo    = (const float*)d_in[8];
    const float* gamma = (const float*)d_in[9];
    const float* beta  = (const float*)d_in[10];
    float* out = (float*)d_out;

    half_t *X16, *Q16, *K16, *V16, *C16, *Wt16;
    float* Hp;
    cudaGetSymbolAddress((void**)&X16, g_X16);
    cudaGetSymbolAddress((void**)&Q16, g_Q16);
    cudaGetSymbolAddress((void**)&K16, g_K16);
    cudaGetSymbolAddress((void**)&V16, g_V16);
    cudaGetSymbolAddress((void**)&C16, g_C16);
    cudaGetSymbolAddress((void**)&Wt16, g_Wt16);
    cudaGetSymbolAddress((void**)&Hp, g_H);

    dim3 tb(32, 8), tg(DM / 32, DM / 32, 4);
    transpose_cvt_kernel<<<tg, tb>>>(Wq, Wk, Wv, Wo, Wt16);

    convert_kernel<<<MTOT * DM / 1024, 256>>>(X, X16);

    cudaFuncSetAttribute(qkv_gemm, cudaFuncAttributeMaxDynamicSharedMemorySize,
                         GSMEM);
    cudaFuncSetAttribute(oproj_gemm, cudaFuncAttributeMaxDynamicSharedMemorySize,
                         GSMEM);
    cudaFuncSetAttribute(attn_mma, cudaFuncAttributeMaxDynamicSharedMemorySize,
                         ASMEM);

    const float qscale = 0.125f * 1.4426950408889634f;  // 1/sqrt(Dh) * log2(e)

    dim3 gq(3 * DM / 128, MTOT / 128);   // 24 x 32 = 768 CTAs
    qkv_gemm<<<gq, 256, GSMEM>>>(X16, Wt16, bq, bk, bv, Q16, K16, V16, qscale);

    dim3 ga(SLEN / 64, NHEAD, 2);        // 1024 CTAs
    attn_mma<<<ga, 128, ASMEM>>>(Q16, K16, V16, C16);

    dim3 go(DM / 128, MTOT / 128);       // 256 CTAs
    oproj_gemm<<<go, 256, GSMEM>>>(C16, Wt16 + 3 * (size_t)DM * DM, bo, X, Hp);

    ln_kernel<<<MTOT, 256>>>(Hp, gamma, beta, out);
}